// round 2
// baseline (speedup 1.0000x reference)
#include <cuda_runtime.h>

// Problem constants
#define BB 2
#define TT 2048
#define HH 16
#define DD 64
#define CC 1024
#define MM (BB*TT)        // 4096 rows
#define NQKV (3*CC)       // 3072

// Scratch (device globals -- no allocation allowed)
__device__ float g_qkv[MM * NQKV];      // [4096, 3072]
__device__ float g_q[BB*HH*TT*DD];      // [B,H,T,D]
__device__ float g_k[BB*HH*TT*DD];
__device__ float g_v[BB*HH*TT*DD];
__device__ float g_att[MM * CC];        // [B,T,C]

// ---------------------------------------------------------------------------
// SGEMM: C[m][n] = sum_k A[m][k] * B[n][k]   (both K-contiguous row-major)
// 64x64 block tile, BK=16, 256 threads, 4x4 per-thread micro-tile.
// ---------------------------------------------------------------------------
__global__ __launch_bounds__(256) void sgemm_nt(
    const float* __restrict__ A, const float* __restrict__ Bm,
    float* __restrict__ Cm, int M, int N, int K)
{
    __shared__ float As[16][68];  // [k][m], padded to 68 (16B-aligned, 2-way max)
    __shared__ float Bs[16][68];  // [k][n]

    const int tid = threadIdx.x;
    const int tx = tid & 15;          // n micro index
    const int ty = tid >> 4;          // m micro index
    const int m0 = blockIdx.y * 64;
    const int n0 = blockIdx.x * 64;

    // load mapping: 256 threads, each loads one float4 of A and B per k-tile
    const int lr = tid >> 2;          // row 0..63
    const int lk = (tid & 3) << 2;    // k 0,4,8,12
    const float* Ap = A  + (size_t)(m0 + lr) * K + lk;
    const float* Bp = Bm + (size_t)(n0 + lr) * K + lk;

    float acc[4][4] = {};

    for (int k0 = 0; k0 < K; k0 += 16) {
        float4 av = *(const float4*)(Ap + k0);
        float4 bv = *(const float4*)(Bp + k0);
        As[lk+0][lr] = av.x; As[lk+1][lr] = av.y;
        As[lk+2][lr] = av.z; As[lk+3][lr] = av.w;
        Bs[lk+0][lr] = bv.x; Bs[lk+1][lr] = bv.y;
        Bs[lk+2][lr] = bv.z; Bs[lk+3][lr] = bv.w;
        __syncthreads();

        #pragma unroll
        for (int k = 0; k < 16; k++) {
            float4 a4 = *(const float4*)&As[k][ty << 2];
            float4 b4 = *(const float4*)&Bs[k][tx << 2];
            float ar[4] = {a4.x, a4.y, a4.z, a4.w};
            float br[4] = {b4.x, b4.y, b4.z, b4.w};
            #pragma unroll
            for (int i = 0; i < 4; i++)
                #pragma unroll
                for (int j = 0; j < 4; j++)
                    acc[i][j] += ar[i] * br[j];
        }
        __syncthreads();
    }

    #pragma unroll
    for (int i = 0; i < 4; i++) {
        float* Cp = Cm + (size_t)(m0 + (ty << 2) + i) * N + n0 + (tx << 2);
        float4 v = {acc[i][0], acc[i][1], acc[i][2], acc[i][3]};
        *(float4*)Cp = v;
    }
}

// ---------------------------------------------------------------------------
// RoPE + scatter qkv -> q/k/v in [B,H,T,D] layout.
// One thread per (b,t,h,d<32) pair; handles d and d+32 of q,k,v.
// rotate_half(x)[d] = -x[d+32] (d<32) ; x[d-32] (d>=32)
// ---------------------------------------------------------------------------
__global__ __launch_bounds__(256) void rope_scatter(
    const float* __restrict__ cosp, const float* __restrict__ sinp)
{
    int idx = blockIdx.x * blockDim.x + threadIdx.x;
    if (idx >= BB * TT * HH * 32) return;
    int d = idx & 31;
    int h = (idx >> 5) & (HH - 1);
    int t = (idx >> 9) & (TT - 1);
    int b = idx >> 20;

    const float* row = g_qkv + (size_t)(b * TT + t) * NQKV;
    int base = h * DD + d;

    float c0 = cosp[t * DD + d],      c1 = cosp[t * DD + d + 32];
    float s0 = sinp[t * DD + d],      s1 = sinp[t * DD + d + 32];

    float q0 = row[base],            q1 = row[base + 32];
    float k0 = row[CC + base],       k1 = row[CC + base + 32];
    float v0 = row[2 * CC + base],   v1 = row[2 * CC + base + 32];

    size_t hoff = ((size_t)(b * HH + h) * TT + t) * DD + d;
    g_q[hoff]      = q0 * c0 - q1 * s0;
    g_q[hoff + 32] = q1 * c1 + q0 * s1;
    g_k[hoff]      = k0 * c0 - k1 * s0;
    g_k[hoff + 32] = k1 * c1 + k0 * s1;
    g_v[hoff]      = v0;
    g_v[hoff + 32] = v1;
}

// ---------------------------------------------------------------------------
// Causal flash attention. One thread = one query row. 128 rows per block.
// K/V staged in smem in 32-row tiles; all inner-loop smem reads broadcast.
// ---------------------------------------------------------------------------
__global__ __launch_bounds__(128) void attn_kernel(float scale)
{
    const int bh = blockIdx.y;               // 0..31  (b*H + h)
    const int q0 = blockIdx.x * 128;
    const int b = bh / HH, h = bh % HH;
    const int t = q0 + threadIdx.x;          // this thread's query row

    const float* Qp = g_q + (size_t)bh * TT * DD;
    const float* Kp = g_k + (size_t)bh * TT * DD;
    const float* Vp = g_v + (size_t)bh * TT * DD;

    __shared__ float Ks[32 * 64];
    __shared__ float Vs[32 * 64];

    float q[64], o[64];
    #pragma unroll
    for (int d = 0; d < 64; d += 4) {
        float4 v4 = *(const float4*)(Qp + (size_t)t * 64 + d);
        q[d] = v4.x; q[d+1] = v4.y; q[d+2] = v4.z; q[d+3] = v4.w;
    }
    #pragma unroll
    for (int d = 0; d < 64; d++) o[d] = 0.f;

    float m = -1e30f, l = 0.f;
    const int kend = q0 + 128;               // exclusive; causal bound for block

    for (int j0 = 0; j0 < kend; j0 += 32) {
        // cooperative load of K,V tiles: 2048 floats each, 4 float4 per thread
        #pragma unroll
        for (int i = 0; i < 4; i++) {
            int off = (i * 128 + threadIdx.x) * 4;
            *(float4*)(Ks + off) = *(const float4*)(Kp + (size_t)j0 * 64 + off);
            *(float4*)(Vs + off) = *(const float4*)(Vp + (size_t)j0 * 64 + off);
        }
        __syncthreads();

        float s[32];
        float tmax = -1e30f;
        #pragma unroll
        for (int j = 0; j < 32; j++) {
            float a0 = 0.f, a1 = 0.f, a2 = 0.f, a3 = 0.f;
            const float* kr = Ks + j * 64;
            #pragma unroll
            for (int d = 0; d < 64; d += 4) {
                a0 += q[d]   * kr[d];
                a1 += q[d+1] * kr[d+1];
                a2 += q[d+2] * kr[d+2];
                a3 += q[d+3] * kr[d+3];
            }
            float acc = ((a0 + a1) + (a2 + a3)) * scale;
            if (j0 + j > t) acc = -1e30f;    // causal mask
            s[j] = acc;
            tmax = fmaxf(tmax, acc);
        }

        float newm = fmaxf(m, tmax);
        float alpha = __expf(m - newm);
        l *= alpha;
        #pragma unroll
        for (int d = 0; d < 64; d++) o[d] *= alpha;

        #pragma unroll
        for (int j = 0; j < 32; j++) {
            float p = __expf(s[j] - newm);
            l += p;
            const float* vr = Vs + j * 64;
            #pragma unroll
            for (int d = 0; d < 64; d++) o[d] += p * vr[d];
        }
        m = newm;
        __syncthreads();
    }

    float inv = 1.f / l;
    float* dst = g_att + (size_t)(b * TT + t) * CC + h * DD;
    #pragma unroll
    for (int d = 0; d < 64; d += 4) {
        float4 v4 = {o[d]*inv, o[d+1]*inv, o[d+2]*inv, o[d+3]*inv};
        *(float4*)(dst + d) = v4;
    }
}

// ---------------------------------------------------------------------------
// Launch
// ---------------------------------------------------------------------------
extern "C" void kernel_launch(void* const* d_in, const int* in_sizes, int n_in,
                              void* d_out, int out_size)
{
    const float* x     = (const float*)d_in[0];   // [2,2048,1024]
    const float* cosp  = (const float*)d_in[1];   // [2048,64]
    const float* sinp  = (const float*)d_in[2];   // [2048,64]
    const float* w_qkv = (const float*)d_in[3];   // [3072,1024]
    const float* w_out = (const float*)d_in[4];   // [1024,1024]
    float* out = (float*)d_out;                   // [2,2048,1024]

    float *p_qkv, *p_att;
    cudaGetSymbolAddress((void**)&p_qkv, g_qkv);
    cudaGetSymbolAddress((void**)&p_att, g_att);

    // 1) qkv = x @ w_qkv^T   : M=4096, N=3072, K=1024
    {
        dim3 grid(NQKV / 64, MM / 64);
        sgemm_nt<<<grid, 256>>>(x, w_qkv, p_qkv, MM, NQKV, CC);
    }

    // 2) RoPE + scatter to [B,H,T,D]
    {
        int total = BB * TT * HH * 32;
        rope_scatter<<<(total + 255) / 256, 256>>>(cosp, sinp);
    }

    // 3) causal flash attention -> g_att [B,T,C]
    {
        dim3 grid(TT / 128, BB * HH);
        attn_kernel<<<grid, 128>>>(0.125f);   // 1/sqrt(64)
    }

    // 4) out = g_att @ w_out^T : M=4096, N=1024, K=1024
    {
        dim3 grid(CC / 64, MM / 64);
        sgemm_nt<<<grid, 256>>>(p_att, w_out, out, MM, CC, CC);
    }
}

// round 3
// speedup vs baseline: 1.5598x; 1.5598x over previous
#include <cuda_runtime.h>
#include <cstdint>

// Problem constants
#define BB 2
#define TT 2048
#define HH 16
#define DD 64
#define CC 1024
#define MM (BB*TT)        // 4096 rows
#define NQKV (3*CC)       // 3072

// Scratch (device globals -- no allocation allowed)
__device__ float g_qkv[MM * NQKV];      // [4096, 3072]
__device__ float g_q[BB*HH*TT*DD];      // [B,H,T,D]
__device__ float g_k[BB*HH*TT*DD];
__device__ float g_v[BB*HH*TT*DD];
__device__ float g_att[MM * CC];        // [B,T,C]

// ---------------------------------------------------------------------------
// TF32 tensor-core GEMM: C[m][n] = sum_k A[m][k] * B[n][k]
// (both operands K-contiguous row-major; B acts as col-major K x N)
// BM=128 BN=128 BK=32, 128 threads (4 warps, each 64x64), 3-stage cp.async.
// smem layout per tile: [row][k] (32 floats/row = 128B) with 16B-granule
// swizzle  granule' = (k>>2) ^ (row&7)  -> STS.128 and frag LDS conflict-free.
// ---------------------------------------------------------------------------
#define BM 128
#define BN 128
#define BK 32
#define STAGES 3
#define TILE_WORDS (BM*BK)          // 4096 floats per matrix tile
#define STAGE_WORDS (2*TILE_WORDS)  // A + B
#define GEMM_SMEM_BYTES (STAGES*STAGE_WORDS*4)   // 98304

__device__ __forceinline__ uint32_t f2tf32(float x) {
    uint32_t r;
    asm("cvt.rna.tf32.f32 %0, %1;" : "=r"(r) : "f"(x));
    return r;
}

__device__ __forceinline__ void mma_tf32(float* d, const uint32_t* a, const uint32_t* b) {
    asm volatile(
        "mma.sync.aligned.m16n8k8.row.col.f32.tf32.tf32.f32 "
        "{%0,%1,%2,%3},{%4,%5,%6,%7},{%8,%9},{%0,%1,%2,%3};\n"
        : "+f"(d[0]), "+f"(d[1]), "+f"(d[2]), "+f"(d[3])
        : "r"(a[0]), "r"(a[1]), "r"(a[2]), "r"(a[3]), "r"(b[0]), "r"(b[1]));
}

__device__ __forceinline__ void cp16(uint32_t smem_addr, const float* gptr) {
    asm volatile("cp.async.cg.shared.global [%0], [%1], 16;\n"
                 :: "r"(smem_addr), "l"(gptr));
}

__global__ __launch_bounds__(128) void gemm_tf32(
    const float* __restrict__ A, const float* __restrict__ Bm,
    float* __restrict__ C, int M, int N, int K)
{
    extern __shared__ float smem[];

    const int tid  = threadIdx.x;
    const int lane = tid & 31;
    const int warp = tid >> 5;
    const int wm = warp & 1;          // 0..1 -> 64 rows each
    const int wn = warp >> 1;         // 0..3 -> wait: 4 warps => wn 0..1
    // 4 warps: 2 (m) x 2 (n); warp tile 64x64
    const int m0 = blockIdx.y * BM;
    const int n0 = blockIdx.x * BN;
    const int gm = lane >> 2;         // 0..7
    const int gk = lane & 3;          // 0..3

    // ---- cp.async mapping: thread loads 8 float4 per matrix per tile ----
    const int lrow = tid >> 3;            // 0..15
    const int lkq  = (tid & 7) << 2;      // 0,4,...,28
    const float* Ag = A  + (size_t)(m0 + lrow) * K + lkq;
    const float* Bg = Bm + (size_t)(n0 + lrow) * K + lkq;
    const int gsw = (((lkq >> 2) ^ (lrow & 7)) << 2);   // swizzled granule word off
    uint32_t smem_u32 = (uint32_t)__cvta_generic_to_shared(smem);

    float acc[2][8][4];
    #pragma unroll
    for (int i = 0; i < 2; i++)
        #pragma unroll
        for (int j = 0; j < 8; j++)
            #pragma unroll
            for (int r = 0; r < 4; r++) acc[i][j][r] = 0.f;

    const int NI = K / BK;

    // issue loads for tile kt into stage s
    auto issue = [&](int s, int kt) {
        uint32_t abase = smem_u32 + (uint32_t)(s * STAGE_WORDS + lrow * BK) * 4 + gsw * 4;
        uint32_t bbase = abase + TILE_WORDS * 4;
        const float* asrc = Ag + kt * BK;
        const float* bsrc = Bg + kt * BK;
        #pragma unroll
        for (int i = 0; i < 8; i++) {
            cp16(abase + i * (16 * BK) * 4, asrc + (size_t)(i * 16) * K);
            cp16(bbase + i * (16 * BK) * 4, bsrc + (size_t)(i * 16) * K);
        }
    };

    issue(0, 0);
    asm volatile("cp.async.commit_group;\n");
    if (NI > 1) issue(1, 1);
    asm volatile("cp.async.commit_group;\n");

    for (int it = 0; it < NI; it++) {
        __syncthreads();                     // all warps done with stage (it+2)%3
        if (it + 2 < NI) issue((it + 2) % STAGES, it + 2);
        asm volatile("cp.async.commit_group;\n");
        asm volatile("cp.async.wait_group 2;\n");
        __syncthreads();                     // stage it%3 visible to all

        const float* As = smem + (it % STAGES) * STAGE_WORDS;
        const float* Bs = As + TILE_WORDS;

        #pragma unroll
        for (int ks = 0; ks < BK; ks += 8) {
            const int k2 = ks >> 2;
            const int off0 = (((k2    ) ^ gm) << 2) + gk;
            const int off1 = (((k2 + 1) ^ gm) << 2) + gk;

            uint32_t af[2][4];
            #pragma unroll
            for (int i = 0; i < 2; i++) {    // 2 m-tiles of 16? -> wait: 64 rows = 4 tiles
                // handled below
            }
            // A fragments: 4 m-tiles (16 rows each) -> 64 rows
            uint32_t a4[4][4];
            #pragma unroll
            for (int i = 0; i < 4; i++) {
                int mb = (wm * 64 + i * 16 + gm) * BK;
                a4[i][0] = f2tf32(As[mb + off0]);
                a4[i][1] = f2tf32(As[mb + 8 * BK + off0]);
                a4[i][2] = f2tf32(As[mb + off1]);
                a4[i][3] = f2tf32(As[mb + 8 * BK + off1]);
            }
            // B fragments: 8 n-tiles (8 cols each) -> 64 cols
            uint32_t b4[8][2];
            #pragma unroll
            for (int j = 0; j < 8; j++) {
                int nb = (wn * 64 + j * 8 + gm) * BK;
                b4[j][0] = f2tf32(Bs[nb + off0]);
                b4[j][1] = f2tf32(Bs[nb + off1]);
            }
            #pragma unroll
            for (int i = 0; i < 4; i++)
                #pragma unroll
                for (int j = 0; j < 8; j++)
                    mma_tf32(acc[i >> 1][(i & 1) * 4 + 0 * 8 + j], a4[i], b4[j]);
        }
    }

    // epilogue: acc[i>>1][(i&1)*4 + j]? -- mapping fixed below to match compute
    #pragma unroll
    for (int i = 0; i < 4; i++) {
        #pragma unroll
        for (int j = 0; j < 8; j++) {
            float* a = acc[i >> 1][(i & 1) * 4 + 0 * 8 + j];
            int r = m0 + wm * 64 + i * 16 + gm;
            int c = n0 + wn * 64 + j * 8 + (gk << 1);
            float2 v0 = {a[0], a[1]};
            float2 v1 = {a[2], a[3]};
            *(float2*)(C + (size_t)r * N + c) = v0;
            *(float2*)(C + (size_t)(r + 8) * N + c) = v1;
        }
    }
}

// NOTE on acc indexing: acc is [2][8][4]; logical tile (i,j), i in 0..3, j in 0..7
// is stored at acc[i>>1][(i&1)*4 ... ] -- this is wrong for j>3. Fixed layout:
// we simply need 32 distinct [4] slots; use acc[i&1][ (i>>1)*... ] -- to avoid
// any aliasing bugs the kernel above uses acc[i>>1][(i&1)*4 + j] which collides
// for j>=4. The actual kernel below redefines it cleanly.

// ---- Clean GEMM (the one actually launched) ----
__global__ __launch_bounds__(128) void gemm_tf32_v2(
    const float* __restrict__ A, const float* __restrict__ Bm,
    float* __restrict__ C, int M, int N, int K)
{
    extern __shared__ float smem[];

    const int tid  = threadIdx.x;
    const int lane = tid & 31;
    const int warp = tid >> 5;
    const int wm = warp & 1;
    const int wn = warp >> 1;         // 0..1
    const int m0 = blockIdx.y * BM;
    const int n0 = blockIdx.x * BN;
    const int gm = lane >> 2;
    const int gk = lane & 3;

    const int lrow = tid >> 3;
    const int lkq  = (tid & 7) << 2;
    const float* Ag = A  + (size_t)(m0 + lrow) * K + lkq;
    const float* Bg = Bm + (size_t)(n0 + lrow) * K + lkq;
    const int gsw = (((lkq >> 2) ^ (lrow & 7)) << 2);
    uint32_t smem_u32 = (uint32_t)__cvta_generic_to_shared(smem);

    float acc[32][4];                 // tile (i,j) -> acc[i*8+j]
    #pragma unroll
    for (int t = 0; t < 32; t++)
        #pragma unroll
        for (int r = 0; r < 4; r++) acc[t][r] = 0.f;

    const int NI = K / BK;

    auto issue = [&](int s, int kt) {
        uint32_t abase = smem_u32 + (uint32_t)(s * STAGE_WORDS + lrow * BK) * 4 + gsw * 4;
        uint32_t bbase = abase + TILE_WORDS * 4;
        const float* asrc = Ag + kt * BK;
        const float* bsrc = Bg + kt * BK;
        #pragma unroll
        for (int i = 0; i < 8; i++) {
            cp16(abase + i * (16 * BK) * 4, asrc + (size_t)(i * 16) * K);
            cp16(bbase + i * (16 * BK) * 4, bsrc + (size_t)(i * 16) * K);
        }
    };

    issue(0, 0);
    asm volatile("cp.async.commit_group;\n");
    if (NI > 1) issue(1, 1);
    asm volatile("cp.async.commit_group;\n");

    for (int it = 0; it < NI; it++) {
        __syncthreads();
        if (it + 2 < NI) issue((it + 2) % STAGES, it + 2);
        asm volatile("cp.async.commit_group;\n");
        asm volatile("cp.async.wait_group 2;\n");
        __syncthreads();

        const float* As = smem + (it % STAGES) * STAGE_WORDS;
        const float* Bs = As + TILE_WORDS;

        #pragma unroll
        for (int ks = 0; ks < BK; ks += 8) {
            const int k2 = ks >> 2;
            const int off0 = (((k2    ) ^ gm) << 2) + gk;
            const int off1 = (((k2 + 1) ^ gm) << 2) + gk;

            uint32_t a4[4][4];
            #pragma unroll
            for (int i = 0; i < 4; i++) {
                int mb = (wm * 64 + i * 16 + gm) * BK;
                a4[i][0] = f2tf32(As[mb + off0]);
                a4[i][1] = f2tf32(As[mb + 8 * BK + off0]);
                a4[i][2] = f2tf32(As[mb + off1]);
                a4[i][3] = f2tf32(As[mb + 8 * BK + off1]);
            }
            uint32_t b4[8][2];
            #pragma unroll
            for (int j = 0; j < 8; j++) {
                int nb = (wn * 64 + j * 8 + gm) * BK;
                b4[j][0] = f2tf32(Bs[nb + off0]);
                b4[j][1] = f2tf32(Bs[nb + off1]);
            }
            #pragma unroll
            for (int i = 0; i < 4; i++)
                #pragma unroll
                for (int j = 0; j < 8; j++)
                    mma_tf32(acc[i * 8 + j], a4[i], b4[j]);
        }
    }

    #pragma unroll
    for (int i = 0; i < 4; i++) {
        #pragma unroll
        for (int j = 0; j < 8; j++) {
            float* a = acc[i * 8 + j];
            int r = m0 + wm * 64 + i * 16 + gm;
            int c = n0 + wn * 64 + j * 8 + (gk << 1);
            float2 v0 = {a[0], a[1]};
            float2 v1 = {a[2], a[3]};
            *(float2*)(C + (size_t)r * N + c) = v0;
            *(float2*)(C + (size_t)(r + 8) * N + c) = v1;
        }
    }
}

// ---------------------------------------------------------------------------
// RoPE + scatter qkv -> q/k/v in [B,H,T,D] layout (unchanged)
// ---------------------------------------------------------------------------
__global__ __launch_bounds__(256) void rope_scatter(
    const float* __restrict__ cosp, const float* __restrict__ sinp)
{
    int idx = blockIdx.x * blockDim.x + threadIdx.x;
    if (idx >= BB * TT * HH * 32) return;
    int d = idx & 31;
    int h = (idx >> 5) & (HH - 1);
    int t = (idx >> 9) & (TT - 1);
    int b = idx >> 20;

    const float* row = g_qkv + (size_t)(b * TT + t) * NQKV;
    int base = h * DD + d;

    float c0 = cosp[t * DD + d],      c1 = cosp[t * DD + d + 32];
    float s0 = sinp[t * DD + d],      s1 = sinp[t * DD + d + 32];

    float q0 = row[base],            q1 = row[base + 32];
    float k0 = row[CC + base],       k1 = row[CC + base + 32];
    float v0 = row[2 * CC + base],   v1 = row[2 * CC + base + 32];

    size_t hoff = ((size_t)(b * HH + h) * TT + t) * DD + d;
    g_q[hoff]      = q0 * c0 - q1 * s0;
    g_q[hoff + 32] = q1 * c1 + q0 * s1;
    g_k[hoff]      = k0 * c0 - k1 * s0;
    g_k[hoff + 32] = k1 * c1 + k0 * s1;
    g_v[hoff]      = v0;
    g_v[hoff + 32] = v1;
}

// ---------------------------------------------------------------------------
// Causal flash attention (unchanged this round; tensor-core version next)
// ---------------------------------------------------------------------------
__global__ __launch_bounds__(128) void attn_kernel(float scale)
{
    const int bh = blockIdx.y;
    const int q0 = blockIdx.x * 128;
    const int b = bh / HH, h = bh % HH;
    const int t = q0 + threadIdx.x;

    const float* Qp = g_q + (size_t)bh * TT * DD;
    const float* Kp = g_k + (size_t)bh * TT * DD;
    const float* Vp = g_v + (size_t)bh * TT * DD;

    __shared__ float Ks[32 * 64];
    __shared__ float Vs[32 * 64];

    float q[64], o[64];
    #pragma unroll
    for (int d = 0; d < 64; d += 4) {
        float4 v4 = *(const float4*)(Qp + (size_t)t * 64 + d);
        q[d] = v4.x; q[d+1] = v4.y; q[d+2] = v4.z; q[d+3] = v4.w;
    }
    #pragma unroll
    for (int d = 0; d < 64; d++) o[d] = 0.f;

    float m = -1e30f, l = 0.f;
    const int kend = q0 + 128;

    for (int j0 = 0; j0 < kend; j0 += 32) {
        #pragma unroll
        for (int i = 0; i < 4; i++) {
            int off = (i * 128 + threadIdx.x) * 4;
            *(float4*)(Ks + off) = *(const float4*)(Kp + (size_t)j0 * 64 + off);
            *(float4*)(Vs + off) = *(const float4*)(Vp + (size_t)j0 * 64 + off);
        }
        __syncthreads();

        float s[32];
        float tmax = -1e30f;
        #pragma unroll
        for (int j = 0; j < 32; j++) {
            float a0 = 0.f, a1 = 0.f, a2 = 0.f, a3 = 0.f;
            const float* kr = Ks + j * 64;
            #pragma unroll
            for (int d = 0; d < 64; d += 4) {
                a0 += q[d]   * kr[d];
                a1 += q[d+1] * kr[d+1];
                a2 += q[d+2] * kr[d+2];
                a3 += q[d+3] * kr[d+3];
            }
            float acc = ((a0 + a1) + (a2 + a3)) * scale;
            if (j0 + j > t) acc = -1e30f;
            s[j] = acc;
            tmax = fmaxf(tmax, acc);
        }

        float newm = fmaxf(m, tmax);
        float alpha = __expf(m - newm);
        l *= alpha;
        #pragma unroll
        for (int d = 0; d < 64; d++) o[d] *= alpha;

        #pragma unroll
        for (int j = 0; j < 32; j++) {
            float p = __expf(s[j] - newm);
            l += p;
            const float* vr = Vs + j * 64;
            #pragma unroll
            for (int d = 0; d < 64; d++) o[d] += p * vr[d];
        }
        m = newm;
        __syncthreads();
    }

    float inv = 1.f / l;
    float* dst = g_att + (size_t)(b * TT + t) * CC + h * DD;
    #pragma unroll
    for (int d = 0; d < 64; d += 4) {
        float4 v4 = {o[d]*inv, o[d+1]*inv, o[d+2]*inv, o[d+3]*inv};
        *(float4*)(dst + d) = v4;
    }
}

// ---------------------------------------------------------------------------
// Launch
// ---------------------------------------------------------------------------
extern "C" void kernel_launch(void* const* d_in, const int* in_sizes, int n_in,
                              void* d_out, int out_size)
{
    const float* x     = (const float*)d_in[0];
    const float* cosp  = (const float*)d_in[1];
    const float* sinp  = (const float*)d_in[2];
    const float* w_qkv = (const float*)d_in[3];
    const float* w_out = (const float*)d_in[4];
    float* out = (float*)d_out;

    float *p_qkv, *p_att;
    cudaGetSymbolAddress((void**)&p_qkv, g_qkv);
    cudaGetSymbolAddress((void**)&p_att, g_att);

    cudaFuncSetAttribute(gemm_tf32_v2,
                         cudaFuncAttributeMaxDynamicSharedMemorySize,
                         GEMM_SMEM_BYTES);

    // 1) qkv = x @ w_qkv^T : M=4096, N=3072, K=1024
    {
        dim3 grid(NQKV / BN, MM / BM);
        gemm_tf32_v2<<<grid, 128, GEMM_SMEM_BYTES>>>(x, w_qkv, p_qkv, MM, NQKV, CC);
    }

    // 2) RoPE + scatter
    {
        int total = BB * TT * HH * 32;
        rope_scatter<<<(total + 255) / 256, 256>>>(cosp, sinp);
    }

    // 3) causal flash attention
    {
        dim3 grid(TT / 128, BB * HH);
        attn_kernel<<<grid, 128>>>(0.125f);
    }

    // 4) out = g_att @ w_out^T : M=4096, N=1024, K=1024
    {
        dim3 grid(CC / BN, MM / BM);
        gemm_tf32_v2<<<grid, 128, GEMM_SMEM_BYTES>>>(p_att, w_out, out, MM, CC, CC);
    }
}

// round 4
// speedup vs baseline: 4.2703x; 2.7378x over previous
#include <cuda_runtime.h>
#include <cstdint>

// Problem constants
#define BB 2
#define TT 2048
#define HH 16
#define DD 64
#define CC 1024
#define MM (BB*TT)        // 4096 rows
#define NQKV (3*CC)       // 3072

// Scratch (device globals -- no allocation allowed)
__device__ float g_qkv[MM * NQKV];      // [4096, 3072]
__device__ float g_q[BB*HH*TT*DD];      // [B,H,T,D] (tf32-rounded)
__device__ float g_k[BB*HH*TT*DD];      // (tf32-rounded)
__device__ float g_v[BB*HH*TT*DD];      // (tf32-rounded)
__device__ float g_att[MM * CC];        // [B,T,C]

__device__ __forceinline__ uint32_t f2tf32(float x) {
    uint32_t r;
    asm("cvt.rna.tf32.f32 %0, %1;" : "=r"(r) : "f"(x));
    return r;
}

__device__ __forceinline__ void mma_tf32(float* d, const uint32_t* a, const uint32_t* b) {
    asm volatile(
        "mma.sync.aligned.m16n8k8.row.col.f32.tf32.tf32.f32 "
        "{%0,%1,%2,%3},{%4,%5,%6,%7},{%8,%9},{%0,%1,%2,%3};\n"
        : "+f"(d[0]), "+f"(d[1]), "+f"(d[2]), "+f"(d[3])
        : "r"(a[0]), "r"(a[1]), "r"(a[2]), "r"(a[3]), "r"(b[0]), "r"(b[1]));
}

__device__ __forceinline__ void cp16(uint32_t smem_addr, const float* gptr) {
    asm volatile("cp.async.cg.shared.global [%0], [%1], 16;\n"
                 :: "r"(smem_addr), "l"(gptr));
}

// ---------------------------------------------------------------------------
// TF32 tensor-core GEMM: C[m][n] = sum_k A[m][k] * B[n][k]
// BM=128 BN=128 BK=32, 128 threads (4 warps, 64x64 each), 3-stage cp.async.
// ---------------------------------------------------------------------------
#define BM 128
#define BN 128
#define BK 32
#define STAGES 3
#define TILE_WORDS (BM*BK)
#define STAGE_WORDS (2*TILE_WORDS)
#define GEMM_SMEM_BYTES (STAGES*STAGE_WORDS*4)   // 98304

__global__ __launch_bounds__(128) void gemm_tf32_v2(
    const float* __restrict__ A, const float* __restrict__ Bm,
    float* __restrict__ C, int M, int N, int K)
{
    extern __shared__ float smem[];

    const int tid  = threadIdx.x;
    const int lane = tid & 31;
    const int warp = tid >> 5;
    const int wm = warp & 1;
    const int wn = warp >> 1;
    const int m0 = blockIdx.y * BM;
    const int n0 = blockIdx.x * BN;
    const int gm = lane >> 2;
    const int gk = lane & 3;

    const int lrow = tid >> 3;
    const int lkq  = (tid & 7) << 2;
    const float* Ag = A  + (size_t)(m0 + lrow) * K + lkq;
    const float* Bg = Bm + (size_t)(n0 + lrow) * K + lkq;
    const int gsw = (((lkq >> 2) ^ (lrow & 7)) << 2);
    uint32_t smem_u32 = (uint32_t)__cvta_generic_to_shared(smem);

    float acc[32][4];
    #pragma unroll
    for (int t = 0; t < 32; t++)
        #pragma unroll
        for (int r = 0; r < 4; r++) acc[t][r] = 0.f;

    const int NI = K / BK;

    auto issue = [&](int s, int kt) {
        uint32_t abase = smem_u32 + (uint32_t)(s * STAGE_WORDS + lrow * BK) * 4 + gsw * 4;
        uint32_t bbase = abase + TILE_WORDS * 4;
        const float* asrc = Ag + kt * BK;
        const float* bsrc = Bg + kt * BK;
        #pragma unroll
        for (int i = 0; i < 8; i++) {
            cp16(abase + i * (16 * BK) * 4, asrc + (size_t)(i * 16) * K);
            cp16(bbase + i * (16 * BK) * 4, bsrc + (size_t)(i * 16) * K);
        }
    };

    issue(0, 0);
    asm volatile("cp.async.commit_group;\n");
    if (NI > 1) issue(1, 1);
    asm volatile("cp.async.commit_group;\n");

    for (int it = 0; it < NI; it++) {
        __syncthreads();
        if (it + 2 < NI) issue((it + 2) % STAGES, it + 2);
        asm volatile("cp.async.commit_group;\n");
        asm volatile("cp.async.wait_group 2;\n");
        __syncthreads();

        const float* As = smem + (it % STAGES) * STAGE_WORDS;
        const float* Bs = As + TILE_WORDS;

        #pragma unroll
        for (int ks = 0; ks < BK; ks += 8) {
            const int k2 = ks >> 2;
            const int off0 = (((k2    ) ^ gm) << 2) + gk;
            const int off1 = (((k2 + 1) ^ gm) << 2) + gk;

            uint32_t a4[4][4];
            #pragma unroll
            for (int i = 0; i < 4; i++) {
                int mb = (wm * 64 + i * 16 + gm) * BK;
                a4[i][0] = f2tf32(As[mb + off0]);
                a4[i][1] = f2tf32(As[mb + 8 * BK + off0]);
                a4[i][2] = f2tf32(As[mb + off1]);
                a4[i][3] = f2tf32(As[mb + 8 * BK + off1]);
            }
            uint32_t b4[8][2];
            #pragma unroll
            for (int j = 0; j < 8; j++) {
                int nb = (wn * 64 + j * 8 + gm) * BK;
                b4[j][0] = f2tf32(Bs[nb + off0]);
                b4[j][1] = f2tf32(Bs[nb + off1]);
            }
            #pragma unroll
            for (int i = 0; i < 4; i++)
                #pragma unroll
                for (int j = 0; j < 8; j++)
                    mma_tf32(acc[i * 8 + j], a4[i], b4[j]);
        }
    }

    #pragma unroll
    for (int i = 0; i < 4; i++) {
        #pragma unroll
        for (int j = 0; j < 8; j++) {
            float* a = acc[i * 8 + j];
            int r = m0 + wm * 64 + i * 16 + gm;
            int c = n0 + wn * 64 + j * 8 + (gk << 1);
            float2 v0 = {a[0], a[1]};
            float2 v1 = {a[2], a[3]};
            *(float2*)(C + (size_t)r * N + c) = v0;
            *(float2*)(C + (size_t)(r + 8) * N + c) = v1;
        }
    }
}

// ---------------------------------------------------------------------------
// RoPE + scatter qkv -> q/k/v in [B,H,T,D]; outputs tf32-rounded.
// ---------------------------------------------------------------------------
__global__ __launch_bounds__(256) void rope_scatter(
    const float* __restrict__ cosp, const float* __restrict__ sinp)
{
    int idx = blockIdx.x * blockDim.x + threadIdx.x;
    if (idx >= BB * TT * HH * 32) return;
    int d = idx & 31;
    int h = (idx >> 5) & (HH - 1);
    int t = (idx >> 9) & (TT - 1);
    int b = idx >> 20;

    const float* row = g_qkv + (size_t)(b * TT + t) * NQKV;
    int base = h * DD + d;

    float c0 = cosp[t * DD + d],      c1 = cosp[t * DD + d + 32];
    float s0 = sinp[t * DD + d],      s1 = sinp[t * DD + d + 32];

    float q0 = row[base],            q1 = row[base + 32];
    float k0 = row[CC + base],       k1 = row[CC + base + 32];
    float v0 = row[2 * CC + base],   v1 = row[2 * CC + base + 32];

    size_t hoff = ((size_t)(b * HH + h) * TT + t) * DD + d;
    g_q[hoff]      = __uint_as_float(f2tf32(q0 * c0 - q1 * s0));
    g_q[hoff + 32] = __uint_as_float(f2tf32(q1 * c1 + q0 * s1));
    g_k[hoff]      = __uint_as_float(f2tf32(k0 * c0 - k1 * s0));
    g_k[hoff + 32] = __uint_as_float(f2tf32(k1 * c1 + k0 * s1));
    g_v[hoff]      = __uint_as_float(f2tf32(v0));
    g_v[hoff + 32] = __uint_as_float(f2tf32(v1));
}

// ---------------------------------------------------------------------------
// Tensor-core causal flash attention.
// Block: 256 thr (8 warps) = 128 queries of one (b,h). Warp w: rows w*16..+15.
// K/V tiles: 64 keys, double-buffered cp.async; smem rows padded to 68 floats.
// ---------------------------------------------------------------------------
#define KT 64
#define KVPAD 68
#define KVTILE (KT*KVPAD)                       // words
#define ATTN_SMEM_BYTES (4*KVTILE*4)            // 2 stages * (K+V) = 69632 B

__global__ __launch_bounds__(256) void attn_mma(float scale)
{
    const int bh = blockIdx.y;
    const int q0 = blockIdx.x * 128;
    const int b = bh >> 4, h = bh & 15;
    const int tid = threadIdx.x;
    const int lane = tid & 31;
    const int w = tid >> 5;
    const int gm = lane >> 2;
    const int gk = lane & 3;

    const float* Qp = g_q + (size_t)bh * TT * DD;
    const float* Kp = g_k + (size_t)bh * TT * DD;
    const float* Vp = g_v + (size_t)bh * TT * DD;

    extern __shared__ float sm[];
    // layout: [stage][K tile | V tile]
    uint32_t smem_u32 = (uint32_t)__cvta_generic_to_shared(sm);

    const int rowA = q0 + w * 16 + gm;      // and rowA+8
    const int wrow_lo = q0 + w * 16;        // warp's lowest row
    const int wrow_hi = wrow_lo + 15;       // warp's highest row

    // Q fragments (already tf32 in gmem)
    uint32_t qf[8][4];
    #pragma unroll
    for (int s = 0; s < 8; s++) {
        qf[s][0] = __float_as_uint(Qp[(size_t)rowA * DD + 8 * s + gk]);
        qf[s][1] = __float_as_uint(Qp[(size_t)(rowA + 8) * DD + 8 * s + gk]);
        qf[s][2] = __float_as_uint(Qp[(size_t)rowA * DD + 8 * s + gk + 4]);
        qf[s][3] = __float_as_uint(Qp[(size_t)(rowA + 8) * DD + 8 * s + gk + 4]);
    }

    float o[8][4];
    #pragma unroll
    for (int n = 0; n < 8; n++)
        #pragma unroll
        for (int r = 0; r < 4; r++) o[n][r] = 0.f;
    float mA = -1e30f, mB = -1e30f, lA = 0.f, lB = 0.f;

    const int ntiles = (q0 + 128) / KT;     // tiles of 64 keys

    // cp.async tile loader: row = (tid>>4)+16i, f4col = tid&15 (conflict-free)
    const int ldr = tid >> 4;
    const int ldc = tid & 15;
    auto issueKV = [&](int jt, int buf) {
        const float* kg = Kp + (size_t)jt * KT * DD;
        const float* vg = Vp + (size_t)jt * KT * DD;
        uint32_t kb = smem_u32 + (uint32_t)(buf * 2 * KVTILE) * 4;
        uint32_t vb = kb + KVTILE * 4;
        #pragma unroll
        for (int i = 0; i < 4; i++) {
            int r = ldr + 16 * i;
            uint32_t so = (uint32_t)(r * KVPAD + ldc * 4) * 4;
            cp16(kb + so, kg + (size_t)r * DD + ldc * 4);
            cp16(vb + so, vg + (size_t)r * DD + ldc * 4);
        }
    };

    issueKV(0, 0);
    asm volatile("cp.async.commit_group;\n");

    for (int jt = 0; jt < ntiles; jt++) {
        if (jt + 1 < ntiles) {
            issueKV(jt + 1, (jt + 1) & 1);
            asm volatile("cp.async.commit_group;\n");
            asm volatile("cp.async.wait_group 1;\n");
        } else {
            asm volatile("cp.async.wait_group 0;\n");
        }
        __syncthreads();

        const int j0 = jt * KT;
        if (j0 <= wrow_hi) {                 // warp has at least one live row
            const float* Ks = sm + ((jt & 1) * 2) * KVTILE;
            const float* Vs = Ks + KVTILE;

            // ---- S = Q @ K^T (per warp: 16 x 64) ----
            float sf[8][4];
            #pragma unroll
            for (int j = 0; j < 8; j++) {
                #pragma unroll
                for (int r = 0; r < 4; r++) sf[j][r] = 0.f;
                #pragma unroll
                for (int s = 0; s < 8; s++) {
                    uint32_t bq[2];
                    const float* kr = Ks + (j * 8 + gm) * KVPAD + 8 * s;
                    bq[0] = __float_as_uint(kr[gk]);
                    bq[1] = __float_as_uint(kr[gk + 4]);
                    mma_tf32(sf[j], qf[s], bq);
                }
            }

            // ---- mask + scale + row max ----
            const bool needmask = (j0 + KT - 1 > wrow_lo);
            float mxA = -1e30f, mxB = -1e30f;
            #pragma unroll
            for (int j = 0; j < 8; j++) {
                #pragma unroll
                for (int e = 0; e < 2; e++) {
                    int col = j0 + 8 * j + 2 * gk + e;
                    float v0 = sf[j][e] * scale;
                    float v1 = sf[j][2 + e] * scale;
                    if (needmask) {
                        if (col > rowA)     v0 = -1e30f;
                        if (col > rowA + 8) v1 = -1e30f;
                    }
                    sf[j][e] = v0; sf[j][2 + e] = v1;
                    mxA = fmaxf(mxA, v0); mxB = fmaxf(mxB, v1);
                }
            }
            mxA = fmaxf(mxA, __shfl_xor_sync(0xffffffffu, mxA, 1));
            mxA = fmaxf(mxA, __shfl_xor_sync(0xffffffffu, mxA, 2));
            mxB = fmaxf(mxB, __shfl_xor_sync(0xffffffffu, mxB, 1));
            mxB = fmaxf(mxB, __shfl_xor_sync(0xffffffffu, mxB, 2));

            float nmA = fmaxf(mA, mxA), nmB = fmaxf(mB, mxB);
            float aA = __expf(mA - nmA), aB = __expf(mB - nmB);
            mA = nmA; mB = nmB;

            // rescale O and l
            #pragma unroll
            for (int n = 0; n < 8; n++) {
                o[n][0] *= aA; o[n][1] *= aA;
                o[n][2] *= aB; o[n][3] *= aB;
            }
            lA *= aA; lB *= aB;

            // ---- P = exp(S - m); accumulate l; convert to tf32 ----
            uint32_t pf[8][4];
            float slA = 0.f, slB = 0.f;
            #pragma unroll
            for (int j = 0; j < 8; j++) {
                float p0 = __expf(sf[j][0] - mA);
                float p1 = __expf(sf[j][1] - mA);
                float p2 = __expf(sf[j][2] - mB);
                float p3 = __expf(sf[j][3] - mB);
                slA += p0 + p1; slB += p2 + p3;
                pf[j][0] = f2tf32(p0); pf[j][1] = f2tf32(p1);
                pf[j][2] = f2tf32(p2); pf[j][3] = f2tf32(p3);
            }
            slA += __shfl_xor_sync(0xffffffffu, slA, 1);
            slA += __shfl_xor_sync(0xffffffffu, slA, 2);
            slB += __shfl_xor_sync(0xffffffffu, slB, 1);
            slB += __shfl_xor_sync(0xffffffffu, slB, 2);
            lA += slA; lB += slB;

            // ---- O += P @ V : per kstep s, build A-frag via shfl ----
            const int srcA = (lane & ~3) | (gk >> 1);
            const int srcB = srcA + 2;
            const bool oddgk = (gk & 1);
            #pragma unroll
            for (int s = 0; s < 8; s++) {
                uint32_t r0 = __shfl_sync(0xffffffffu, pf[s][0], srcA);
                uint32_t r1 = __shfl_sync(0xffffffffu, pf[s][1], srcA);
                uint32_t r2 = __shfl_sync(0xffffffffu, pf[s][0], srcB);
                uint32_t r3 = __shfl_sync(0xffffffffu, pf[s][1], srcB);
                uint32_t r4 = __shfl_sync(0xffffffffu, pf[s][2], srcA);
                uint32_t r5 = __shfl_sync(0xffffffffu, pf[s][3], srcA);
                uint32_t r6 = __shfl_sync(0xffffffffu, pf[s][2], srcB);
                uint32_t r7 = __shfl_sync(0xffffffffu, pf[s][3], srcB);
                uint32_t af[4];
                af[0] = oddgk ? r1 : r0;   // P[gm][8s+gk]
                af[1] = oddgk ? r5 : r4;   // P[gm+8][8s+gk]
                af[2] = oddgk ? r3 : r2;   // P[gm][8s+gk+4]
                af[3] = oddgk ? r7 : r6;   // P[gm+8][8s+gk+4]
                #pragma unroll
                for (int n = 0; n < 8; n++) {
                    uint32_t bv[2];
                    const float* vr = Vs + (8 * s + gk) * KVPAD + 8 * n + gm;
                    bv[0] = __float_as_uint(vr[0]);
                    bv[1] = __float_as_uint(vr[4 * KVPAD]);
                    mma_tf32(o[n], af, bv);
                }
            }
        }
        __syncthreads();
    }

    // epilogue
    float invA = 1.f / lA, invB = 1.f / lB;
    float* dstA = g_att + (size_t)(b * TT + rowA) * CC + h * DD;
    float* dstB = g_att + (size_t)(b * TT + rowA + 8) * CC + h * DD;
    #pragma unroll
    for (int n = 0; n < 8; n++) {
        int c = 8 * n + 2 * gk;
        float2 v0 = {o[n][0] * invA, o[n][1] * invA};
        float2 v1 = {o[n][2] * invB, o[n][3] * invB};
        *(float2*)(dstA + c) = v0;
        *(float2*)(dstB + c) = v1;
    }
}

// ---------------------------------------------------------------------------
// Launch
// ---------------------------------------------------------------------------
extern "C" void kernel_launch(void* const* d_in, const int* in_sizes, int n_in,
                              void* d_out, int out_size)
{
    const float* x     = (const float*)d_in[0];
    const float* cosp  = (const float*)d_in[1];
    const float* sinp  = (const float*)d_in[2];
    const float* w_qkv = (const float*)d_in[3];
    const float* w_out = (const float*)d_in[4];
    float* out = (float*)d_out;

    float *p_qkv, *p_att;
    cudaGetSymbolAddress((void**)&p_qkv, g_qkv);
    cudaGetSymbolAddress((void**)&p_att, g_att);

    cudaFuncSetAttribute(gemm_tf32_v2,
                         cudaFuncAttributeMaxDynamicSharedMemorySize,
                         GEMM_SMEM_BYTES);
    cudaFuncSetAttribute(attn_mma,
                         cudaFuncAttributeMaxDynamicSharedMemorySize,
                         ATTN_SMEM_BYTES);

    // 1) qkv = x @ w_qkv^T : M=4096, N=3072, K=1024
    {
        dim3 grid(NQKV / BN, MM / BM);
        gemm_tf32_v2<<<grid, 128, GEMM_SMEM_BYTES>>>(x, w_qkv, p_qkv, MM, NQKV, CC);
    }

    // 2) RoPE + scatter (tf32-rounded outputs)
    {
        int total = BB * TT * HH * 32;
        rope_scatter<<<(total + 255) / 256, 256>>>(cosp, sinp);
    }

    // 3) tensor-core causal flash attention
    {
        dim3 grid(TT / 128, BB * HH);
        attn_mma<<<grid, 256, ATTN_SMEM_BYTES>>>(0.125f);
    }

    // 4) out = g_att @ w_out^T : M=4096, N=1024, K=1024
    {
        dim3 grid(CC / BN, MM / BM);
        gemm_tf32_v2<<<grid, 128, GEMM_SMEM_BYTES>>>(p_att, w_out, out, MM, CC, CC);
    }
}

// round 5
// speedup vs baseline: 4.6629x; 1.0919x over previous
#include <cuda_runtime.h>
#include <cstdint>

// Problem constants
#define BB 2
#define TT 2048
#define HH 16
#define DD 64
#define CC 1024
#define MM (BB*TT)        // 4096 rows
#define NQKV (3*CC)       // 3072

// Scratch (device globals -- no allocation allowed)
__device__ float g_qkv[MM * NQKV];      // [4096, 3072]
__device__ float g_q[BB*HH*TT*DD];      // [B,H,T,D] (tf32-rounded)
__device__ float g_k[BB*HH*TT*DD];      // (tf32-rounded)
__device__ float g_v[BB*HH*TT*DD];      // (tf32-rounded)
__device__ float g_att[MM * CC];        // [B,T,C]

__device__ __forceinline__ uint32_t f2tf32(float x) {
    uint32_t r;
    asm("cvt.rna.tf32.f32 %0, %1;" : "=r"(r) : "f"(x));
    return r;
}

__device__ __forceinline__ float ex2(float x) {
    float y;
    asm("ex2.approx.ftz.f32 %0, %1;" : "=f"(y) : "f"(x));
    return y;
}

__device__ __forceinline__ void mma_tf32(float* d, const uint32_t* a, const uint32_t* b) {
    asm volatile(
        "mma.sync.aligned.m16n8k8.row.col.f32.tf32.tf32.f32 "
        "{%0,%1,%2,%3},{%4,%5,%6,%7},{%8,%9},{%0,%1,%2,%3};\n"
        : "+f"(d[0]), "+f"(d[1]), "+f"(d[2]), "+f"(d[3])
        : "r"(a[0]), "r"(a[1]), "r"(a[2]), "r"(a[3]), "r"(b[0]), "r"(b[1]));
}

__device__ __forceinline__ void cp16(uint32_t smem_addr, const float* gptr) {
    asm volatile("cp.async.cg.shared.global [%0], [%1], 16;\n"
                 :: "r"(smem_addr), "l"(gptr));
}

// ---------------------------------------------------------------------------
// TF32 tensor-core GEMM: C[m][n] = sum_k A[m][k] * B[n][k]
// BM=128 BN=128 BK=32, 128 threads (4 warps, 64x64 each), 3-stage cp.async.
// ---------------------------------------------------------------------------
#define BM 128
#define BN 128
#define BK 32
#define STAGES 3
#define TILE_WORDS (BM*BK)
#define STAGE_WORDS (2*TILE_WORDS)
#define GEMM_SMEM_BYTES (STAGES*STAGE_WORDS*4)   // 98304

__global__ __launch_bounds__(128) void gemm_tf32_v2(
    const float* __restrict__ A, const float* __restrict__ Bm,
    float* __restrict__ C, int M, int N, int K)
{
    extern __shared__ float smem[];

    const int tid  = threadIdx.x;
    const int lane = tid & 31;
    const int warp = tid >> 5;
    const int wm = warp & 1;
    const int wn = warp >> 1;
    const int m0 = blockIdx.y * BM;
    const int n0 = blockIdx.x * BN;
    const int gm = lane >> 2;
    const int gk = lane & 3;

    const int lrow = tid >> 3;
    const int lkq  = (tid & 7) << 2;
    const float* Ag = A  + (size_t)(m0 + lrow) * K + lkq;
    const float* Bg = Bm + (size_t)(n0 + lrow) * K + lkq;
    const int gsw = (((lkq >> 2) ^ (lrow & 7)) << 2);
    uint32_t smem_u32 = (uint32_t)__cvta_generic_to_shared(smem);

    float acc[32][4];
    #pragma unroll
    for (int t = 0; t < 32; t++)
        #pragma unroll
        for (int r = 0; r < 4; r++) acc[t][r] = 0.f;

    const int NI = K / BK;

    auto issue = [&](int s, int kt) {
        uint32_t abase = smem_u32 + (uint32_t)(s * STAGE_WORDS + lrow * BK) * 4 + gsw * 4;
        uint32_t bbase = abase + TILE_WORDS * 4;
        const float* asrc = Ag + kt * BK;
        const float* bsrc = Bg + kt * BK;
        #pragma unroll
        for (int i = 0; i < 8; i++) {
            cp16(abase + i * (16 * BK) * 4, asrc + (size_t)(i * 16) * K);
            cp16(bbase + i * (16 * BK) * 4, bsrc + (size_t)(i * 16) * K);
        }
    };

    issue(0, 0);
    asm volatile("cp.async.commit_group;\n");
    if (NI > 1) issue(1, 1);
    asm volatile("cp.async.commit_group;\n");

    for (int it = 0; it < NI; it++) {
        __syncthreads();
        if (it + 2 < NI) issue((it + 2) % STAGES, it + 2);
        asm volatile("cp.async.commit_group;\n");
        asm volatile("cp.async.wait_group 2;\n");
        __syncthreads();

        const float* As = smem + (it % STAGES) * STAGE_WORDS;
        const float* Bs = As + TILE_WORDS;

        #pragma unroll
        for (int ks = 0; ks < BK; ks += 8) {
            const int k2 = ks >> 2;
            const int off0 = (((k2    ) ^ gm) << 2) + gk;
            const int off1 = (((k2 + 1) ^ gm) << 2) + gk;

            uint32_t a4[4][4];
            #pragma unroll
            for (int i = 0; i < 4; i++) {
                int mb = (wm * 64 + i * 16 + gm) * BK;
                a4[i][0] = f2tf32(As[mb + off0]);
                a4[i][1] = f2tf32(As[mb + 8 * BK + off0]);
                a4[i][2] = f2tf32(As[mb + off1]);
                a4[i][3] = f2tf32(As[mb + 8 * BK + off1]);
            }
            uint32_t b4[8][2];
            #pragma unroll
            for (int j = 0; j < 8; j++) {
                int nb = (wn * 64 + j * 8 + gm) * BK;
                b4[j][0] = f2tf32(Bs[nb + off0]);
                b4[j][1] = f2tf32(Bs[nb + off1]);
            }
            #pragma unroll
            for (int i = 0; i < 4; i++)
                #pragma unroll
                for (int j = 0; j < 8; j++)
                    mma_tf32(acc[i * 8 + j], a4[i], b4[j]);
        }
    }

    #pragma unroll
    for (int i = 0; i < 4; i++) {
        #pragma unroll
        for (int j = 0; j < 8; j++) {
            float* a = acc[i * 8 + j];
            int r = m0 + wm * 64 + i * 16 + gm;
            int c = n0 + wn * 64 + j * 8 + (gk << 1);
            float2 v0 = {a[0], a[1]};
            float2 v1 = {a[2], a[3]};
            *(float2*)(C + (size_t)r * N + c) = v0;
            *(float2*)(C + (size_t)(r + 8) * N + c) = v1;
        }
    }
}

// ---------------------------------------------------------------------------
// RoPE + scatter qkv -> q/k/v in [B,H,T,D]; outputs tf32-rounded.
// ---------------------------------------------------------------------------
__global__ __launch_bounds__(256) void rope_scatter(
    const float* __restrict__ cosp, const float* __restrict__ sinp)
{
    int idx = blockIdx.x * blockDim.x + threadIdx.x;
    if (idx >= BB * TT * HH * 32) return;
    int d = idx & 31;
    int h = (idx >> 5) & (HH - 1);
    int t = (idx >> 9) & (TT - 1);
    int b = idx >> 20;

    const float* row = g_qkv + (size_t)(b * TT + t) * NQKV;
    int base = h * DD + d;

    float c0 = cosp[t * DD + d],      c1 = cosp[t * DD + d + 32];
    float s0 = sinp[t * DD + d],      s1 = sinp[t * DD + d + 32];

    float q0 = row[base],            q1 = row[base + 32];
    float k0 = row[CC + base],       k1 = row[CC + base + 32];
    float v0 = row[2 * CC + base],   v1 = row[2 * CC + base + 32];

    size_t hoff = ((size_t)(b * HH + h) * TT + t) * DD + d;
    g_q[hoff]      = __uint_as_float(f2tf32(q0 * c0 - q1 * s0));
    g_q[hoff + 32] = __uint_as_float(f2tf32(q1 * c1 + q0 * s1));
    g_k[hoff]      = __uint_as_float(f2tf32(k0 * c0 - k1 * s0));
    g_k[hoff + 32] = __uint_as_float(f2tf32(k1 * c1 + k0 * s1));
    g_v[hoff]      = __uint_as_float(f2tf32(v0));
    g_v[hoff + 32] = __uint_as_float(f2tf32(v1));
}

// ---------------------------------------------------------------------------
// Tensor-core causal flash attention, v2.
// Block: 256 thr (8 warps) = 128 queries of one (b,h). Warp w: rows w*16..+15.
// K/V tiles: 64 keys double-buffered cp.async.
//   K rows padded to 68 floats (QK B-frag banks 4*gm+gk: conflict-free)
//   V rows padded to 72 floats (PV B-frag banks 8*gk+gm: conflict-free)
// S processed in 2x32-key chunks (sf/pf 16 regs) -> fits 2 blocks/SM @128 regs.
// Softmax in log2 domain (scale*log2e folded in), raw ex2.approx.
// ---------------------------------------------------------------------------
#define KT 64
#define KPAD 68
#define VPAD 72
#define KTILEW (KT*KPAD)
#define VTILEW (KT*VPAD)
#define STAGEW (KTILEW+VTILEW)
#define ATTN_SMEM_BYTES (2*STAGEW*4)   // 71680

__global__ __launch_bounds__(256, 2) void attn_mma(float kscale)
{
    const int bh = blockIdx.y;
    const int q0 = (gridDim.x - 1 - blockIdx.x) * 128;   // heavy blocks first
    const int b = bh >> 4, h = bh & 15;
    const int tid = threadIdx.x;
    const int lane = tid & 31;
    const int w = tid >> 5;
    const int gm = lane >> 2;
    const int gk = lane & 3;

    const float* Qp = g_q + (size_t)bh * TT * DD;
    const float* Kp = g_k + (size_t)bh * TT * DD;
    const float* Vp = g_v + (size_t)bh * TT * DD;

    extern __shared__ float sm[];
    uint32_t smem_u32 = (uint32_t)__cvta_generic_to_shared(sm);

    const int rowA = q0 + w * 16 + gm;      // and rowA+8
    const int wrow_lo = q0 + w * 16;
    const int wrow_hi = wrow_lo + 15;

    // Q fragments (already tf32 in gmem)
    uint32_t qf[8][4];
    #pragma unroll
    for (int s = 0; s < 8; s++) {
        qf[s][0] = __float_as_uint(Qp[(size_t)rowA * DD + 8 * s + gk]);
        qf[s][1] = __float_as_uint(Qp[(size_t)(rowA + 8) * DD + 8 * s + gk]);
        qf[s][2] = __float_as_uint(Qp[(size_t)rowA * DD + 8 * s + gk + 4]);
        qf[s][3] = __float_as_uint(Qp[(size_t)(rowA + 8) * DD + 8 * s + gk + 4]);
    }

    float o[8][4];
    #pragma unroll
    for (int n = 0; n < 8; n++)
        #pragma unroll
        for (int r = 0; r < 4; r++) o[n][r] = 0.f;
    float mA = -1e30f, mB = -1e30f, lA = 0.f, lB = 0.f;

    const int ntiles = (q0 + 128) / KT;

    // cp.async tile loader: row = (tid>>4)+16i, f4col = tid&15
    const int ldr = tid >> 4;
    const int ldc = tid & 15;
    auto issueKV = [&](int jt, int buf) {
        const float* kg = Kp + (size_t)jt * KT * DD;
        const float* vg = Vp + (size_t)jt * KT * DD;
        uint32_t kb = smem_u32 + (uint32_t)(buf * STAGEW) * 4;
        uint32_t vb = kb + KTILEW * 4;
        #pragma unroll
        for (int i = 0; i < 4; i++) {
            int r = ldr + 16 * i;
            cp16(kb + (uint32_t)(r * KPAD + ldc * 4) * 4, kg + (size_t)r * DD + ldc * 4);
            cp16(vb + (uint32_t)(r * VPAD + ldc * 4) * 4, vg + (size_t)r * DD + ldc * 4);
        }
    };

    issueKV(0, 0);
    asm volatile("cp.async.commit_group;\n");

    for (int jt = 0; jt < ntiles; jt++) {
        if (jt + 1 < ntiles) {
            issueKV(jt + 1, (jt + 1) & 1);
            asm volatile("cp.async.commit_group;\n");
            asm volatile("cp.async.wait_group 1;\n");
        } else {
            asm volatile("cp.async.wait_group 0;\n");
        }
        __syncthreads();

        const float* Ks = sm + (jt & 1) * STAGEW;
        const float* Vs = Ks + KTILEW;
        const int j0 = jt * KT;

        #pragma unroll
        for (int c = 0; c < 2; c++) {
            const int c0 = j0 + 32 * c;               // chunk key base
            if (c0 > wrow_hi) break;                  // fully masked chunk

            // ---- S chunk = Q @ K^T (16 x 32) ----
            float sf[4][4];
            #pragma unroll
            for (int j = 0; j < 4; j++) {
                #pragma unroll
                for (int r = 0; r < 4; r++) sf[j][r] = 0.f;
                #pragma unroll
                for (int s = 0; s < 8; s++) {
                    uint32_t bq[2];
                    const float* kr = Ks + (32 * c + j * 8 + gm) * KPAD + 8 * s;
                    bq[0] = __float_as_uint(kr[gk]);
                    bq[1] = __float_as_uint(kr[gk + 4]);
                    mma_tf32(sf[j], qf[s], bq);
                }
            }

            // ---- mask + scale (log2 domain) + row max ----
            const bool needmask = (c0 + 31 > wrow_lo);
            float mxA = -1e30f, mxB = -1e30f;
            #pragma unroll
            for (int j = 0; j < 4; j++) {
                #pragma unroll
                for (int e = 0; e < 2; e++) {
                    int col = c0 + 8 * j + 2 * gk + e;
                    float v0 = sf[j][e] * kscale;
                    float v1 = sf[j][2 + e] * kscale;
                    if (needmask) {
                        if (col > rowA)     v0 = -1e30f;
                        if (col > rowA + 8) v1 = -1e30f;
                    }
                    sf[j][e] = v0; sf[j][2 + e] = v1;
                    mxA = fmaxf(mxA, v0); mxB = fmaxf(mxB, v1);
                }
            }
            mxA = fmaxf(mxA, __shfl_xor_sync(0xffffffffu, mxA, 1));
            mxA = fmaxf(mxA, __shfl_xor_sync(0xffffffffu, mxA, 2));
            mxB = fmaxf(mxB, __shfl_xor_sync(0xffffffffu, mxB, 1));
            mxB = fmaxf(mxB, __shfl_xor_sync(0xffffffffu, mxB, 2));

            float nmA = fmaxf(mA, mxA), nmB = fmaxf(mB, mxB);
            float aA = ex2(mA - nmA), aB = ex2(mB - nmB);
            mA = nmA; mB = nmB;

            #pragma unroll
            for (int n = 0; n < 8; n++) {
                o[n][0] *= aA; o[n][1] *= aA;
                o[n][2] *= aB; o[n][3] *= aB;
            }
            lA *= aA; lB *= aB;

            // ---- P = exp2(S - m); accumulate l; to tf32 (in place) ----
            uint32_t pf[4][4];
            float slA = 0.f, slB = 0.f;
            #pragma unroll
            for (int j = 0; j < 4; j++) {
                float p0 = ex2(sf[j][0] - mA);
                float p1 = ex2(sf[j][1] - mA);
                float p2 = ex2(sf[j][2] - mB);
                float p3 = ex2(sf[j][3] - mB);
                slA += p0 + p1; slB += p2 + p3;
                pf[j][0] = f2tf32(p0); pf[j][1] = f2tf32(p1);
                pf[j][2] = f2tf32(p2); pf[j][3] = f2tf32(p3);
            }
            slA += __shfl_xor_sync(0xffffffffu, slA, 1);
            slA += __shfl_xor_sync(0xffffffffu, slA, 2);
            slB += __shfl_xor_sync(0xffffffffu, slB, 1);
            slB += __shfl_xor_sync(0xffffffffu, slB, 2);
            lA += slA; lB += slB;

            // ---- O += P @ V : per kstep s2, A-frag via shfl transpose ----
            const int srcA = (lane & ~3) | (gk >> 1);
            const int srcB = srcA + 2;
            const bool oddgk = (gk & 1);
            #pragma unroll
            for (int s2 = 0; s2 < 4; s2++) {
                uint32_t r0 = __shfl_sync(0xffffffffu, pf[s2][0], srcA);
                uint32_t r1 = __shfl_sync(0xffffffffu, pf[s2][1], srcA);
                uint32_t r2 = __shfl_sync(0xffffffffu, pf[s2][0], srcB);
                uint32_t r3 = __shfl_sync(0xffffffffu, pf[s2][1], srcB);
                uint32_t r4 = __shfl_sync(0xffffffffu, pf[s2][2], srcA);
                uint32_t r5 = __shfl_sync(0xffffffffu, pf[s2][3], srcA);
                uint32_t r6 = __shfl_sync(0xffffffffu, pf[s2][2], srcB);
                uint32_t r7 = __shfl_sync(0xffffffffu, pf[s2][3], srcB);
                uint32_t af[4];
                af[0] = oddgk ? r1 : r0;
                af[1] = oddgk ? r5 : r4;
                af[2] = oddgk ? r3 : r2;
                af[3] = oddgk ? r7 : r6;
                #pragma unroll
                for (int n = 0; n < 8; n++) {
                    uint32_t bv[2];
                    const float* vr = Vs + (32 * c + 8 * s2 + gk) * VPAD + 8 * n + gm;
                    bv[0] = __float_as_uint(vr[0]);
                    bv[1] = __float_as_uint(vr[4 * VPAD]);
                    mma_tf32(o[n], af, bv);
                }
            }
        }
        __syncthreads();
    }

    // epilogue
    float invA = 1.f / lA, invB = 1.f / lB;
    float* dstA = g_att + (size_t)(b * TT + rowA) * CC + h * DD;
    float* dstB = g_att + (size_t)(b * TT + rowA + 8) * CC + h * DD;
    #pragma unroll
    for (int n = 0; n < 8; n++) {
        int cix = 8 * n + 2 * gk;
        float2 v0 = {o[n][0] * invA, o[n][1] * invA};
        float2 v1 = {o[n][2] * invB, o[n][3] * invB};
        *(float2*)(dstA + cix) = v0;
        *(float2*)(dstB + cix) = v1;
    }
}

// ---------------------------------------------------------------------------
// Launch
// ---------------------------------------------------------------------------
extern "C" void kernel_launch(void* const* d_in, const int* in_sizes, int n_in,
                              void* d_out, int out_size)
{
    const float* x     = (const float*)d_in[0];
    const float* cosp  = (const float*)d_in[1];
    const float* sinp  = (const float*)d_in[2];
    const float* w_qkv = (const float*)d_in[3];
    const float* w_out = (const float*)d_in[4];
    float* out = (float*)d_out;

    float *p_qkv, *p_att;
    cudaGetSymbolAddress((void**)&p_qkv, g_qkv);
    cudaGetSymbolAddress((void**)&p_att, g_att);

    cudaFuncSetAttribute(gemm_tf32_v2,
                         cudaFuncAttributeMaxDynamicSharedMemorySize,
                         GEMM_SMEM_BYTES);
    cudaFuncSetAttribute(attn_mma,
                         cudaFuncAttributeMaxDynamicSharedMemorySize,
                         ATTN_SMEM_BYTES);

    // 1) qkv = x @ w_qkv^T : M=4096, N=3072, K=1024
    {
        dim3 grid(NQKV / BN, MM / BM);
        gemm_tf32_v2<<<grid, 128, GEMM_SMEM_BYTES>>>(x, w_qkv, p_qkv, MM, NQKV, CC);
    }

    // 2) RoPE + scatter (tf32-rounded outputs)
    {
        int total = BB * TT * HH * 32;
        rope_scatter<<<(total + 255) / 256, 256>>>(cosp, sinp);
    }

    // 3) tensor-core causal flash attention (log2-domain scale)
    {
        dim3 grid(TT / 128, BB * HH);
        attn_mma<<<grid, 256, ATTN_SMEM_BYTES>>>(0.125f * 1.44269504f);
    }

    // 4) out = g_att @ w_out^T : M=4096, N=1024, K=1024
    {
        dim3 grid(CC / BN, MM / BM);
        gemm_tf32_v2<<<grid, 128, GEMM_SMEM_BYTES>>>(p_att, w_out, out, MM, CC, CC);
    }
}

// round 6
// speedup vs baseline: 5.4230x; 1.1630x over previous
#include <cuda_runtime.h>
#include <cuda_fp16.h>
#include <cstdint>

// Problem constants
#define BB 2
#define TT 2048
#define HH 16
#define DD 64
#define CC 1024
#define MM (BB*TT)        // 4096 rows
#define NQKV (3*CC)       // 3072

// Scratch (device globals -- no allocation allowed)
__device__ float  g_qkv[MM * NQKV];        // [4096, 3072]
__device__ __half g_qh[BB*HH*TT*DD];       // [bh][t][d] fp16
__device__ __half g_kh[BB*HH*TT*DD];       // [bh][t][d] fp16
__device__ __half g_vh[BB*HH*DD*TT];       // [bh][d][t] fp16 (d-major!)
__device__ float  g_att[MM * CC];          // [B,T,C]

__device__ __forceinline__ uint32_t f2tf32(float x) {
    uint32_t r;
    asm("cvt.rna.tf32.f32 %0, %1;" : "=r"(r) : "f"(x));
    return r;
}

__device__ __forceinline__ float ex2(float x) {
    float y;
    asm("ex2.approx.ftz.f32 %0, %1;" : "=f"(y) : "f"(x));
    return y;
}

__device__ __forceinline__ void mma_tf32(float* d, const uint32_t* a, const uint32_t* b) {
    asm volatile(
        "mma.sync.aligned.m16n8k8.row.col.f32.tf32.tf32.f32 "
        "{%0,%1,%2,%3},{%4,%5,%6,%7},{%8,%9},{%0,%1,%2,%3};\n"
        : "+f"(d[0]), "+f"(d[1]), "+f"(d[2]), "+f"(d[3])
        : "r"(a[0]), "r"(a[1]), "r"(a[2]), "r"(a[3]), "r"(b[0]), "r"(b[1]));
}

__device__ __forceinline__ void mma_f16(float* d, const uint32_t* a, const uint32_t* b) {
    asm volatile(
        "mma.sync.aligned.m16n8k16.row.col.f32.f16.f16.f32 "
        "{%0,%1,%2,%3},{%4,%5,%6,%7},{%8,%9},{%0,%1,%2,%3};\n"
        : "+f"(d[0]), "+f"(d[1]), "+f"(d[2]), "+f"(d[3])
        : "r"(a[0]), "r"(a[1]), "r"(a[2]), "r"(a[3]), "r"(b[0]), "r"(b[1]));
}

__device__ __forceinline__ void cp16(uint32_t smem_addr, const void* gptr) {
    asm volatile("cp.async.cg.shared.global [%0], [%1], 16;\n"
                 :: "r"(smem_addr), "l"(gptr));
}

// ---------------------------------------------------------------------------
// TF32 tensor-core GEMM (unchanged, proven): C[m][n] = sum_k A[m][k]*B[n][k]
// ---------------------------------------------------------------------------
#define BM 128
#define BN 128
#define BK 32
#define STAGES 3
#define TILE_WORDS (BM*BK)
#define STAGE_WORDS (2*TILE_WORDS)
#define GEMM_SMEM_BYTES (STAGES*STAGE_WORDS*4)   // 98304

__global__ __launch_bounds__(128) void gemm_tf32_v2(
    const float* __restrict__ A, const float* __restrict__ Bm,
    float* __restrict__ C, int M, int N, int K)
{
    extern __shared__ float smem[];

    const int tid  = threadIdx.x;
    const int lane = tid & 31;
    const int warp = tid >> 5;
    const int wm = warp & 1;
    const int wn = warp >> 1;
    const int m0 = blockIdx.y * BM;
    const int n0 = blockIdx.x * BN;
    const int gm = lane >> 2;
    const int gk = lane & 3;

    const int lrow = tid >> 3;
    const int lkq  = (tid & 7) << 2;
    const float* Ag = A  + (size_t)(m0 + lrow) * K + lkq;
    const float* Bg = Bm + (size_t)(n0 + lrow) * K + lkq;
    const int gsw = (((lkq >> 2) ^ (lrow & 7)) << 2);
    uint32_t smem_u32 = (uint32_t)__cvta_generic_to_shared(smem);

    float acc[32][4];
    #pragma unroll
    for (int t = 0; t < 32; t++)
        #pragma unroll
        for (int r = 0; r < 4; r++) acc[t][r] = 0.f;

    const int NI = K / BK;

    auto issue = [&](int s, int kt) {
        uint32_t abase = smem_u32 + (uint32_t)(s * STAGE_WORDS + lrow * BK) * 4 + gsw * 4;
        uint32_t bbase = abase + TILE_WORDS * 4;
        const float* asrc = Ag + kt * BK;
        const float* bsrc = Bg + kt * BK;
        #pragma unroll
        for (int i = 0; i < 8; i++) {
            cp16(abase + i * (16 * BK) * 4, asrc + (size_t)(i * 16) * K);
            cp16(bbase + i * (16 * BK) * 4, bsrc + (size_t)(i * 16) * K);
        }
    };

    issue(0, 0);
    asm volatile("cp.async.commit_group;\n");
    if (NI > 1) issue(1, 1);
    asm volatile("cp.async.commit_group;\n");

    for (int it = 0; it < NI; it++) {
        __syncthreads();
        if (it + 2 < NI) issue((it + 2) % STAGES, it + 2);
        asm volatile("cp.async.commit_group;\n");
        asm volatile("cp.async.wait_group 2;\n");
        __syncthreads();

        const float* As = smem + (it % STAGES) * STAGE_WORDS;
        const float* Bs = As + TILE_WORDS;

        #pragma unroll
        for (int ks = 0; ks < BK; ks += 8) {
            const int k2 = ks >> 2;
            const int off0 = (((k2    ) ^ gm) << 2) + gk;
            const int off1 = (((k2 + 1) ^ gm) << 2) + gk;

            uint32_t a4[4][4];
            #pragma unroll
            for (int i = 0; i < 4; i++) {
                int mb = (wm * 64 + i * 16 + gm) * BK;
                a4[i][0] = f2tf32(As[mb + off0]);
                a4[i][1] = f2tf32(As[mb + 8 * BK + off0]);
                a4[i][2] = f2tf32(As[mb + off1]);
                a4[i][3] = f2tf32(As[mb + 8 * BK + off1]);
            }
            uint32_t b4[8][2];
            #pragma unroll
            for (int j = 0; j < 8; j++) {
                int nb = (wn * 64 + j * 8 + gm) * BK;
                b4[j][0] = f2tf32(Bs[nb + off0]);
                b4[j][1] = f2tf32(Bs[nb + off1]);
            }
            #pragma unroll
            for (int i = 0; i < 4; i++)
                #pragma unroll
                for (int j = 0; j < 8; j++)
                    mma_tf32(acc[i * 8 + j], a4[i], b4[j]);
        }
    }

    #pragma unroll
    for (int i = 0; i < 4; i++) {
        #pragma unroll
        for (int j = 0; j < 8; j++) {
            float* a = acc[i * 8 + j];
            int r = m0 + wm * 64 + i * 16 + gm;
            int c = n0 + wn * 64 + j * 8 + (gk << 1);
            float2 v0 = {a[0], a[1]};
            float2 v1 = {a[2], a[3]};
            *(float2*)(C + (size_t)r * N + c) = v0;
            *(float2*)(C + (size_t)(r + 8) * N + c) = v1;
        }
    }
}

// ---------------------------------------------------------------------------
// RoPE + scatter q,k -> fp16 [bh][t][d]. (V handled by v_transpose.)
// ---------------------------------------------------------------------------
__global__ __launch_bounds__(256) void rope_scatter(
    const float* __restrict__ cosp, const float* __restrict__ sinp)
{
    int idx = blockIdx.x * blockDim.x + threadIdx.x;
    if (idx >= BB * TT * HH * 32) return;
    int d = idx & 31;
    int h = (idx >> 5) & (HH - 1);
    int t = (idx >> 9) & (TT - 1);
    int b = idx >> 20;

    const float* row = g_qkv + (size_t)(b * TT + t) * NQKV;
    int base = h * DD + d;

    float c0 = cosp[t * DD + d],      c1 = cosp[t * DD + d + 32];
    float s0 = sinp[t * DD + d],      s1 = sinp[t * DD + d + 32];

    float q0 = row[base],            q1 = row[base + 32];
    float k0 = row[CC + base],       k1 = row[CC + base + 32];

    size_t hoff = ((size_t)(b * HH + h) * TT + t) * DD + d;
    g_qh[hoff]      = __float2half(q0 * c0 - q1 * s0);
    g_qh[hoff + 32] = __float2half(q1 * c1 + q0 * s1);
    g_kh[hoff]      = __float2half(k0 * c0 - k1 * s0);
    g_kh[hoff + 32] = __float2half(k1 * c1 + k0 * s1);
}

// ---------------------------------------------------------------------------
// V transpose: g_qkv v-part [b,t,h*64+d] -> g_vh [bh][d][t] fp16.
// Block: 256 thr, tile = 32 t x 64 d of one (b,h).
// ---------------------------------------------------------------------------
__global__ __launch_bounds__(256) void v_transpose()
{
    __shared__ __half s[64][40];       // [d][t-pad]

    const int bh = blockIdx.y;
    const int b = bh >> 4, h = bh & 15;
    const int t0 = blockIdx.x * 32;
    const int tid = threadIdx.x;

    // load: thread -> (t = tid>>3, d8 = (tid&7)*8): 8 consecutive d
    {
        int t = tid >> 3;
        int d8 = (tid & 7) << 3;
        const float* src = g_qkv + (size_t)(b * TT + t0 + t) * NQKV + 2 * CC + h * DD + d8;
        float4 v0 = *(const float4*)(src);
        float4 v1 = *(const float4*)(src + 4);
        s[d8 + 0][t] = __float2half(v0.x);
        s[d8 + 1][t] = __float2half(v0.y);
        s[d8 + 2][t] = __float2half(v0.z);
        s[d8 + 3][t] = __float2half(v0.w);
        s[d8 + 4][t] = __float2half(v1.x);
        s[d8 + 5][t] = __float2half(v1.y);
        s[d8 + 6][t] = __float2half(v1.z);
        s[d8 + 7][t] = __float2half(v1.w);
    }
    __syncthreads();

    // write: thread -> (d = tid>>2, tq = (tid&3)*8): 8 halves = 16B
    {
        int d = tid >> 2;
        int tq = (tid & 3) << 3;
        uint4 v = *(const uint4*)&s[d][tq];
        __half* dst = g_vh + ((size_t)bh * DD + d) * TT + t0 + tq;
        *(uint4*)dst = v;
    }
}

// ---------------------------------------------------------------------------
// fp16 tensor-core causal flash attention.
// Block: 256 thr (8 warps) = 128 queries of one (b,h). Warp w: rows w*16..+15.
// K tile [64 key][72 halves pad] (t-major), V tile [64 d][72 halves pad]
// (d-major), both double-buffered cp.async. All frag LDS bank-conflict-free
// (bank = 4*gm+gk+const bijection at 144B pitch).
// P C-frag packs directly into m16n8k16 A-frag halves: zero shfl transpose.
// Softmax in log2 domain.
// ---------------------------------------------------------------------------
#define KT 64
#define PADH 72
#define KTILE_B (KT*PADH*2)          // 9216 bytes
#define STAGE_B (2*KTILE_B)          // K + V
#define ATTN_SMEM_BYTES (2*STAGE_B)  // 36864

__global__ __launch_bounds__(256, 2) void attn_mma_h(float kscale)
{
    const int bh = blockIdx.y;
    const int q0 = (gridDim.x - 1 - blockIdx.x) * 128;   // heavy blocks first
    const int b = bh >> 4, h = bh & 15;
    const int tid = threadIdx.x;
    const int lane = tid & 31;
    const int w = tid >> 5;
    const int gm = lane >> 2;
    const int gk = lane & 3;

    const __half* Qp = g_qh + (size_t)bh * TT * DD;
    const __half* Kp = g_kh + (size_t)bh * TT * DD;
    const __half* Vp = g_vh + (size_t)bh * DD * TT;   // d-major

    extern __shared__ char smc[];
    uint32_t smem_u32 = (uint32_t)__cvta_generic_to_shared(smc);

    const int rowA = q0 + w * 16 + gm;      // and rowA+8
    const int wrow_lo = q0 + w * 16;
    const int wrow_hi = wrow_lo + 15;

    // Q fragments: 4 k-steps x 4 half2
    uint32_t qf[4][4];
    #pragma unroll
    for (int s = 0; s < 4; s++) {
        const __half* r0 = Qp + (size_t)rowA * DD + 16 * s + 2 * gk;
        const __half* r1 = Qp + (size_t)(rowA + 8) * DD + 16 * s + 2 * gk;
        qf[s][0] = *(const uint32_t*)r0;
        qf[s][1] = *(const uint32_t*)r1;
        qf[s][2] = *(const uint32_t*)(r0 + 8);
        qf[s][3] = *(const uint32_t*)(r1 + 8);
    }

    float o[8][4];
    #pragma unroll
    for (int n = 0; n < 8; n++)
        #pragma unroll
        for (int r = 0; r < 4; r++) o[n][r] = 0.f;
    float mA = -1e30f, mB = -1e30f, lA = 0.f, lB = 0.f;

    const int ntiles = (q0 + 128) / KT;

    // cp.async loader: row = tid&63, two 16B chunks (c2, c2+4) per matrix
    const int ldrow = tid & 63;
    const int ldc2 = tid >> 6;          // 0..3
    auto issueKV = [&](int jt, int buf) {
        const char* kg = (const char*)(Kp + (size_t)jt * KT * DD);   // 128B rows
        const char* vg = (const char*)(Vp + jt * KT);                 // col offset
        uint32_t kb = smem_u32 + buf * STAGE_B;
        uint32_t vb = kb + KTILE_B;
        uint32_t so = (uint32_t)(ldrow * (PADH * 2) + ldc2 * 16);
        cp16(kb + so,      kg + ldrow * 128 + ldc2 * 16);
        cp16(kb + so + 64, kg + ldrow * 128 + ldc2 * 16 + 64);
        cp16(vb + so,      vg + (size_t)ldrow * (TT * 2) + ldc2 * 16);
        cp16(vb + so + 64, vg + (size_t)ldrow * (TT * 2) + ldc2 * 16 + 64);
    };

    issueKV(0, 0);
    asm volatile("cp.async.commit_group;\n");

    for (int jt = 0; jt < ntiles; jt++) {
        if (jt + 1 < ntiles) {
            issueKV(jt + 1, (jt + 1) & 1);
            asm volatile("cp.async.commit_group;\n");
            asm volatile("cp.async.wait_group 1;\n");
        } else {
            asm volatile("cp.async.wait_group 0;\n");
        }
        __syncthreads();

        const char* Ks = smc + (jt & 1) * STAGE_B;
        const char* Vs = Ks + KTILE_B;
        const int j0 = jt * KT;

        #pragma unroll
        for (int c = 0; c < 2; c++) {
            const int c0 = j0 + 32 * c;               // chunk key base
            if (c0 > wrow_hi) break;                  // fully masked chunk

            // ---- S chunk = Q @ K^T (16 x 32): 16 MMAs ----
            float sf[4][4];
            #pragma unroll
            for (int j = 0; j < 4; j++) {
                #pragma unroll
                for (int r = 0; r < 4; r++) sf[j][r] = 0.f;
                const char* kr = Ks + (32 * c + 8 * j + gm) * (PADH * 2) + 4 * gk;
                #pragma unroll
                for (int s = 0; s < 4; s++) {
                    uint32_t bq[2];
                    bq[0] = *(const uint32_t*)(kr + 32 * s);
                    bq[1] = *(const uint32_t*)(kr + 32 * s + 16);
                    mma_f16(sf[j], qf[s], bq);
                }
            }

            // ---- mask + scale (log2 domain) + row max ----
            const bool needmask = (c0 + 31 > wrow_lo);
            float mxA = -1e30f, mxB = -1e30f;
            #pragma unroll
            for (int j = 0; j < 4; j++) {
                #pragma unroll
                for (int e = 0; e < 2; e++) {
                    int col = c0 + 8 * j + 2 * gk + e;
                    float v0 = sf[j][e] * kscale;
                    float v1 = sf[j][2 + e] * kscale;
                    if (needmask) {
                        if (col > rowA)     v0 = -1e30f;
                        if (col > rowA + 8) v1 = -1e30f;
                    }
                    sf[j][e] = v0; sf[j][2 + e] = v1;
                    mxA = fmaxf(mxA, v0); mxB = fmaxf(mxB, v1);
                }
            }
            mxA = fmaxf(mxA, __shfl_xor_sync(0xffffffffu, mxA, 1));
            mxA = fmaxf(mxA, __shfl_xor_sync(0xffffffffu, mxA, 2));
            mxB = fmaxf(mxB, __shfl_xor_sync(0xffffffffu, mxB, 1));
            mxB = fmaxf(mxB, __shfl_xor_sync(0xffffffffu, mxB, 2));

            float nmA = fmaxf(mA, mxA), nmB = fmaxf(mB, mxB);
            float aA = ex2(mA - nmA), aB = ex2(mB - nmB);
            mA = nmA; mB = nmB;

            #pragma unroll
            for (int n = 0; n < 8; n++) {
                o[n][0] *= aA; o[n][1] *= aA;
                o[n][2] *= aB; o[n][3] *= aB;
            }
            lA *= aA; lB *= aB;

            // ---- P = exp2(S - m); pack directly into fp16 A-frags ----
            uint32_t ph[4][2];                         // [j][row half]
            float slA = 0.f, slB = 0.f;
            #pragma unroll
            for (int j = 0; j < 4; j++) {
                float p0 = ex2(sf[j][0] - mA);
                float p1 = ex2(sf[j][1] - mA);
                float p2 = ex2(sf[j][2] - mB);
                float p3 = ex2(sf[j][3] - mB);
                slA += p0 + p1; slB += p2 + p3;
                __half2 h01 = __floats2half2_rn(p0, p1);
                __half2 h23 = __floats2half2_rn(p2, p3);
                ph[j][0] = *(const uint32_t*)&h01;
                ph[j][1] = *(const uint32_t*)&h23;
            }
            slA += __shfl_xor_sync(0xffffffffu, slA, 1);
            slA += __shfl_xor_sync(0xffffffffu, slA, 2);
            slB += __shfl_xor_sync(0xffffffffu, slB, 1);
            slB += __shfl_xor_sync(0xffffffffu, slB, 2);
            lA += slA; lB += slB;

            // ---- O += P @ V : A-frag = packed P (no shfl), B from Vs ----
            #pragma unroll
            for (int s2 = 0; s2 < 2; s2++) {
                uint32_t af[4] = { ph[2 * s2][0], ph[2 * s2][1],
                                   ph[2 * s2 + 1][0], ph[2 * s2 + 1][1] };
                const char* vcol = Vs + (32 * c + 16 * s2 + 2 * gk) * 2;
                #pragma unroll
                for (int n = 0; n < 8; n++) {
                    const char* vr = vcol + (8 * n + gm) * (PADH * 2);
                    uint32_t bv[2];
                    bv[0] = *(const uint32_t*)(vr);
                    bv[1] = *(const uint32_t*)(vr + 16);
                    mma_f16(o[n], af, bv);
                }
            }
        }
        __syncthreads();
    }

    // epilogue
    float invA = 1.f / lA, invB = 1.f / lB;
    float* dstA = g_att + (size_t)(b * TT + rowA) * CC + h * DD;
    float* dstB = g_att + (size_t)(b * TT + rowA + 8) * CC + h * DD;
    #pragma unroll
    for (int n = 0; n < 8; n++) {
        int cix = 8 * n + 2 * gk;
        float2 v0 = {o[n][0] * invA, o[n][1] * invA};
        float2 v1 = {o[n][2] * invB, o[n][3] * invB};
        *(float2*)(dstA + cix) = v0;
        *(float2*)(dstB + cix) = v1;
    }
}

// ---------------------------------------------------------------------------
// Launch
// ---------------------------------------------------------------------------
extern "C" void kernel_launch(void* const* d_in, const int* in_sizes, int n_in,
                              void* d_out, int out_size)
{
    const float* x     = (const float*)d_in[0];
    const float* cosp  = (const float*)d_in[1];
    const float* sinp  = (const float*)d_in[2];
    const float* w_qkv = (const float*)d_in[3];
    const float* w_out = (const float*)d_in[4];
    float* out = (float*)d_out;

    float *p_qkv, *p_att;
    cudaGetSymbolAddress((void**)&p_qkv, g_qkv);
    cudaGetSymbolAddress((void**)&p_att, g_att);

    cudaFuncSetAttribute(gemm_tf32_v2,
                         cudaFuncAttributeMaxDynamicSharedMemorySize,
                         GEMM_SMEM_BYTES);
    cudaFuncSetAttribute(attn_mma_h,
                         cudaFuncAttributeMaxDynamicSharedMemorySize,
                         ATTN_SMEM_BYTES);

    // 1) qkv = x @ w_qkv^T : M=4096, N=3072, K=1024
    {
        dim3 grid(NQKV / BN, MM / BM);
        gemm_tf32_v2<<<grid, 128, GEMM_SMEM_BYTES>>>(x, w_qkv, p_qkv, MM, NQKV, CC);
    }

    // 2a) RoPE q,k -> fp16 [bh][t][d]
    {
        int total = BB * TT * HH * 32;
        rope_scatter<<<(total + 255) / 256, 256>>>(cosp, sinp);
    }
    // 2b) V -> fp16 [bh][d][t]
    {
        dim3 grid(TT / 32, BB * HH);
        v_transpose<<<grid, 256>>>();
    }

    // 3) fp16 tensor-core causal flash attention (log2-domain scale)
    {
        dim3 grid(TT / 128, BB * HH);
        attn_mma_h<<<grid, 256, ATTN_SMEM_BYTES>>>(0.125f * 1.44269504f);
    }

    // 4) out = g_att @ w_out^T : M=4096, N=1024, K=1024
    {
        dim3 grid(CC / BN, MM / BM);
        gemm_tf32_v2<<<grid, 128, GEMM_SMEM_BYTES>>>(p_att, w_out, out, MM, CC, CC);
    }
}